// round 4
// baseline (speedup 1.0000x reference)
#include <cuda_runtime.h>
#include <math.h>

#define EPSF 1e-7f
#define POS_THR 0.5f
#define NEG_THR 0.4f
#define ALPHA_F 0.25f

#define MAXN 32
#define MAXP 100

// Contiguous scratch so one memset clears everything.
struct Scratch {
    unsigned long long gtkey[MAXN * MAXP]; // packed (iou_bits<<32)|~a per GT
    double             sumn[MAXN * 3];     // per-batch partial sums
    int                poscnt[MAXN];
    int                done;
};
__device__ Scratch g_s;

__device__ __forceinline__ float clipf(float x) {
    return fminf(fmaxf(x, EPSF), 1.0f - EPSF);
}

__device__ __forceinline__ float focal_term(float t, float qraw) {
    float q  = clipf(qraw);
    float pt = t * q + (1.f - t) * (1.f - q);
    float at = t * ALPHA_F + (1.f - t) * (1.f - ALPHA_F);
    float om = 1.f - pt;
    return -at * om * om * __logf(pt);
}

__device__ __forceinline__ float ciou(float4 bt, float4 bp) {
    float ix1 = fmaxf(bt.x, bp.x), iy1 = fmaxf(bt.y, bp.y);
    float ix2 = fminf(bt.z, bp.z), iy2 = fminf(bt.w, bp.w);
    float inter = fmaxf(ix2 - ix1, 0.f) * fmaxf(iy2 - iy1, 0.f);
    float wt = bt.z - bt.x, ht = bt.w - bt.y;
    float wp = bp.z - bp.x, hp = bp.w - bp.y;
    float uni = wt * ht + wp * hp - inter + EPSF;
    float iou = inter / uni;
    float cw = fmaxf(bt.z, bp.z) - fminf(bt.x, bp.x);
    float ch = fmaxf(bt.w, bp.w) - fminf(bt.y, bp.y);
    float c2 = cw * cw + ch * ch + EPSF;
    float dx = bt.x + bt.z - bp.x - bp.z;
    float dy = bt.y + bt.w - bp.y - bp.w;
    float rho2 = (dx * dx + dy * dy) * 0.25f;
    float dat = atanf(wt / (ht + EPSF)) - atanf(wp / (hp + EPSF));
    float v = (4.0f / (float)(M_PI * M_PI)) * dat * dat;
    float alpha = v / (1.0f - iou + v + EPSF);
    return 1.0f - iou + rho2 / c2 + alpha * v;
}

// ---------------------------------------------------------------------------
// Fused pass: per-anchor assignment (threshold only) + losses + per-GT best.
// ---------------------------------------------------------------------------
__global__ void fused_kernel(const float* __restrict__ y_true,
                             const float4* __restrict__ bbox_true,
                             const float* __restrict__ conf_pred,
                             const float* __restrict__ logit_pred,
                             const float4* __restrict__ bbox_pred,
                             const float4* __restrict__ anchors,
                             int N, int P, int A, int C) {
    int n = blockIdx.y;
    int tid = threadIdx.x;
    int a = blockIdx.x * blockDim.x + tid;

    __shared__ float4 s_gt[MAXP];     // compacted valid GTs (ascending p)
    __shared__ float  s_area[MAXP];
    __shared__ short  s_orig[MAXP];
    __shared__ unsigned long long s_key[MAXP];
    __shared__ int    s_wcnt[4];
    __shared__ int    s_nv;

    {   // stable compaction (P <= 128)
        bool v = false; float4 g = {0,0,0,0};
        if (tid < P) {
            g = bbox_true[n * P + tid];
            v = (g.x > 0.f) || (g.y > 0.f) || (g.z > 0.f) || (g.w > 0.f);
            s_key[tid] = 0ull;
        }
        if (tid < 128) {
            unsigned m = __ballot_sync(0xffffffffu, v);
            int w = tid >> 5, lane = tid & 31;
            if (lane == 0) s_wcnt[w] = __popc(m);
            __syncthreads();
            if (tid == 0) s_nv = s_wcnt[0] + s_wcnt[1] + s_wcnt[2] + s_wcnt[3];
            int off = 0;
            for (int i = 0; i < w; i++) off += s_wcnt[i];
            if (v) {
                int pos = off + __popc(m & ((1u << lane) - 1u));
                s_gt[pos] = g;
                s_area[pos] = (g.z - g.x) * (g.w - g.y);
                s_orig[pos] = (short)tid;
            }
        } else {
            __syncthreads();
        }
        __syncthreads();
    }
    int nv = s_nv;

    float score = 0.f, cls = 0.f, bl = 0.f;
    int posc = 0;

    if (a < A) {
        float4 an = anchors[a];
        float areaa = (an.z - an.x) * (an.w - an.y);
        float bi = -1.0f, bd = 1.0f;   // best iou = bi/bd, first-index wins
        int tixc = 0;
        unsigned inv_a = ~(unsigned)a;
        #pragma unroll 2
        for (int i = 0; i < nv; i++) {
            float4 g = s_gt[i];
            float iw = fmaxf(fminf(an.z, g.z) - fmaxf(an.x, g.x), 0.f);
            float ih = fmaxf(fminf(an.w, g.w) - fmaxf(an.y, g.y), 0.f);
            float inter = iw * ih;
            float denom = areaa + s_area[i] - inter + EPSF;
            if (inter * bd > bi * denom) { bi = inter; bd = denom; tixc = i; }
            if (inter > 0.f) {
                float iou = inter / denom;
                unsigned long long key =
                    ((unsigned long long)__float_as_uint(iou) << 32) | inv_a;
                atomicMax(&s_key[i], key);
            }
        }
        float maxiou = (nv > 0) ? (bi / bd) : -1.0f;

        bool pos = (maxiou >= POS_THR);
        bool neg = (maxiou < NEG_THR);

        float pc = clipf(conf_pred[(size_t)n * A + a]);
        if (pos)      score = -__logf(pc);
        else if (neg) score = -__logf(1.0f - pc);

        if (pos) {
            posc = 1;
            int tix = (int)s_orig[tixc];
            const float4* qrow = reinterpret_cast<const float4*>(
                logit_pred + ((size_t)n * A + a) * C);
            const float4* trow = reinterpret_cast<const float4*>(
                y_true + ((size_t)n * P + tix) * C);
            for (int c4 = 0; c4 < C / 4; c4++) {
                float4 tv = trow[c4];
                float4 qv = qrow[c4];
                cls += focal_term(tv.x, qv.x) + focal_term(tv.y, qv.y)
                     + focal_term(tv.z, qv.z) + focal_term(tv.w, qv.w);
            }
            bl = ciou(s_gt[tixc], bbox_pred[(size_t)n * A + a]);
        }
    }

    // Block reduction -> per-(n,component) atomics
    unsigned mask = 0xffffffffu;
    #pragma unroll
    for (int off = 16; off > 0; off >>= 1) {
        score += __shfl_down_sync(mask, score, off);
        cls   += __shfl_down_sync(mask, cls, off);
        bl    += __shfl_down_sync(mask, bl, off);
        posc  += __shfl_down_sync(mask, posc, off);
    }
    __shared__ float rs0[8], rs1[8], rs2[8];
    __shared__ int   ri[8];
    int lane = tid & 31, warp = tid >> 5;
    if (lane == 0) { rs0[warp] = score; rs1[warp] = cls; rs2[warp] = bl; ri[warp] = posc; }
    __syncthreads();
    if (tid == 0) {
        float t0 = 0.f, t1 = 0.f, t2 = 0.f; int tc = 0;
        for (int w = 0; w < 8; w++) { t0 += rs0[w]; t1 += rs1[w]; t2 += rs2[w]; tc += ri[w]; }
        atomicAdd(&g_s.sumn[n * 3 + 0], (double)t0);
        atomicAdd(&g_s.sumn[n * 3 + 1], (double)t1);
        atomicAdd(&g_s.sumn[n * 3 + 2], (double)t2);
        if (tc) atomicAdd(&g_s.poscnt[n], tc);
    }
    // per-GT best anchor -> global
    if (tid < nv && s_key[tid] != 0ull)
        atomicMax(&g_s.gtkey[n * P + (int)s_orig[tid]], s_key[tid]);
}

// ---------------------------------------------------------------------------
// Fixup: apply low-quality overrides as deltas (<= P winners per image),
// then last block finalizes the three outputs.
// ---------------------------------------------------------------------------
__global__ void fixup_kernel(const float* __restrict__ y_true,
                             const float4* __restrict__ bbox_true,
                             const float* __restrict__ conf_pred,
                             const float* __restrict__ logit_pred,
                             const float4* __restrict__ bbox_pred,
                             const float4* __restrict__ anchors,
                             float* __restrict__ out,
                             int N, int P, int A, int C) {
    int n = blockIdx.x;
    int tid = threadIdx.x;
    int lane = tid & 31, warp = tid >> 5;

    __shared__ float4 s_raw[MAXP];
    __shared__ int    s_ba[MAXP];     // best anchor per GT, -1 if none
    __shared__ short  s_wp[MAXP];     // winner GT indices (last-wins unique)
    __shared__ int    s_nw;
    __shared__ bool   s_last;
    __shared__ double s_acc[3];       // block-local deltas? no — direct atomics

    if (tid < P) {
        s_raw[tid] = bbox_true[n * P + tid];
        unsigned long long key = g_s.gtkey[n * P + tid];
        s_ba[tid] = (key != 0ull) ? (int)(~(unsigned)key) : -1;
    }
    __syncthreads();
    // winner = lowq GT with no later GT mapping to the same anchor (last-wins)
    bool win = false;
    if (tid < P && s_ba[tid] >= 0) {
        win = true;
        for (int q = tid + 1; q < P; q++)
            if (s_ba[q] == s_ba[tid]) { win = false; break; }
    }
    __syncthreads();
    if (tid == 0) {
        int nw = 0;
        for (int p = 0; p < P; p++)
            if (s_ba[p] >= 0) {
                bool w = true;
                for (int q = p + 1; q < P; q++)
                    if (s_ba[q] == s_ba[p]) { w = false; break; }
                if (w) s_wp[nw++] = (short)p;
            }
        s_nw = nw;
    }
    __syncthreads();
    int nw = s_nw;

    double d0 = 0.0, d1 = 0.0, d2 = 0.0;
    int dpc = 0;

    for (int wi = warp; wi < nw; wi += blockDim.x >> 5) {
        int p = s_wp[wi];          // new tix
        int a = s_ba[p];
        // lane0: recompute threshold argmax EXACTLY as fused_kernel did
        float maxiou; int old_tix;
        if (lane == 0) {
            float4 an = anchors[a];
            float areaa = (an.z - an.x) * (an.w - an.y);
            float bi = -1.0f, bd = 1.0f; int tix = 0; int cnt = 0;
            for (int pp = 0; pp < P; pp++) {
                float4 g = s_raw[pp];
                if (!((g.x > 0.f) || (g.y > 0.f) || (g.z > 0.f) || (g.w > 0.f)))
                    continue;
                float areab = (g.z - g.x) * (g.w - g.y);
                float iw = fmaxf(fminf(an.z, g.z) - fmaxf(an.x, g.x), 0.f);
                float ih = fmaxf(fminf(an.w, g.w) - fmaxf(an.y, g.y), 0.f);
                float inter = iw * ih;
                float denom = areaa + areab - inter + EPSF;
                if (inter * bd > bi * denom) { bi = inter; bd = denom; tix = pp; }
                cnt++;
            }
            maxiou = (cnt > 0) ? (bi / bd) : -1.0f;
            old_tix = tix;
        }
        maxiou  = __shfl_sync(0xffffffffu, maxiou, 0);
        old_tix = __shfl_sync(0xffffffffu, old_tix, 0);

        bool pos_t = (maxiou >= POS_THR);
        bool neg_t = (maxiou < NEG_THR);

        if (lane == 0) {
            float pc = clipf(conf_pred[(size_t)n * A + a]);
            if (!pos_t) {
                float ds = -__logf(pc);               // add pos score
                if (neg_t) ds -= -__logf(1.0f - pc);  // remove neg score
                d0 += (double)ds;
                dpc += 1;
            }
        }
        if (!pos_t || old_tix != p) {
            // cls delta: new focal (tix=p) minus old focal (if was pos)
            const float* qrow = logit_pred + ((size_t)n * A + a) * C;
            const float* trow_new = y_true + ((size_t)n * P + p) * C;
            const float* trow_old = y_true + ((size_t)n * P + old_tix) * C;
            float dc = 0.f;
            for (int c = lane; c < C; c += 32) {
                float q = qrow[c];
                dc += focal_term(trow_new[c], q);
                if (pos_t) dc -= focal_term(trow_old[c], q);
            }
            #pragma unroll
            for (int off = 16; off > 0; off >>= 1)
                dc += __shfl_down_sync(0xffffffffu, dc, off);
            if (lane == 0) {
                d1 += (double)dc;
                float4 bp = bbox_pred[(size_t)n * A + a];
                float db = ciou(s_raw[p], bp);
                if (pos_t) db -= ciou(s_raw[old_tix], bp);
                d2 += (double)db;
            }
        }
    }
    if (lane == 0) {
        if (d0 != 0.0) atomicAdd(&g_s.sumn[n * 3 + 0], d0);
        if (d1 != 0.0) atomicAdd(&g_s.sumn[n * 3 + 1], d1);
        if (d2 != 0.0) atomicAdd(&g_s.sumn[n * 3 + 2], d2);
        if (dpc)       atomicAdd(&g_s.poscnt[n], dpc);
    }
    __syncthreads();
    if (tid == 0) {
        __threadfence();
        int d = atomicAdd(&g_s.done, 1);
        s_last = (d == N - 1);
    }
    __syncthreads();
    if (s_last && tid == 0) {
        __threadfence();
        double af = 0.0, t0 = 0.0, t1 = 0.0, t2 = 0.0;
        for (int nn = 0; nn < N; nn++) {
            int c = g_s.poscnt[nn];
            af += (double)(c > 1 ? c : 1);
            t0 += g_s.sumn[nn * 3 + 0];
            t1 += g_s.sumn[nn * 3 + 1];
            t2 += g_s.sumn[nn * 3 + 2];
        }
        double s[3] = {t0, t1, t2};
        #pragma unroll
        for (int i = 0; i < 3; i++) {
            float v = (float)(s[i] / af);
            if (isnan(v) || isinf(v)) v = 0.f;
            out[i] = v;
        }
    }
    (void)s_acc; (void)win;
}

extern "C" void kernel_launch(void* const* d_in, const int* in_sizes, int n_in,
                              void* d_out, int out_size) {
    const float* y_true    = (const float*)d_in[0];
    const float* bbox_true = (const float*)d_in[1];
    const float* conf_pred = (const float*)d_in[2];
    const float* logit     = (const float*)d_in[3];
    const float* bbox_pred = (const float*)d_in[4];
    const float* anchors   = (const float*)d_in[5];

    int A = in_sizes[5] / 4;
    int N = in_sizes[2] / A;
    int C = in_sizes[3] / (N * A);
    int P = in_sizes[1] / (N * 4);

    void* scratch_addr = nullptr;
    cudaGetSymbolAddress(&scratch_addr, g_s);
    cudaMemsetAsync(scratch_addr, 0, sizeof(Scratch));

    int gx = (A + 255) / 256;
    fused_kernel<<<dim3(gx, N), 256>>>(
        y_true, (const float4*)bbox_true, conf_pred, logit,
        (const float4*)bbox_pred, (const float4*)anchors, N, P, A, C);
    fixup_kernel<<<N, 128>>>(
        y_true, (const float4*)bbox_true, conf_pred, logit,
        (const float4*)bbox_pred, (const float4*)anchors,
        (float*)d_out, N, P, A, C);
}

// round 6
// speedup vs baseline: 2.5748x; 2.5748x over previous
#include <cuda_runtime.h>
#include <math.h>

#define EPSF 1e-7f
#define POS_THR 0.5f
#define NEG_THR 0.4f
#define ALPHA_F 0.25f

#define MAXN 32
#define MAXP 100
#define MAXA 25600

// Contiguous scratch so one memset clears everything that must start at 0.
struct Scratch {
    unsigned long long gtkey[MAXN * MAXP]; // packed (iou_bits<<32)|~a per GT
    double             sumn[MAXN * 3];     // per-batch partial sums
    int                poscnt[MAXN];
    int                done;
};
__device__ Scratch g_s;
__device__ float2  g_amax[MAXN * MAXA];    // {maxiou, int_as_float(tix)} per anchor
                                           // (fully rewritten each run before any read)

__device__ __forceinline__ float clipf(float x) {
    return fminf(fmaxf(x, EPSF), 1.0f - EPSF);
}

__device__ __forceinline__ float focal_term(float t, float qraw) {
    float q  = clipf(qraw);
    float pt = t * q + (1.f - t) * (1.f - q);
    float at = t * ALPHA_F + (1.f - t) * (1.f - ALPHA_F);
    float om = 1.f - pt;
    return -at * om * om * __logf(pt);
}

__device__ __forceinline__ float ciou(float4 bt, float4 bp) {
    float ix1 = fmaxf(bt.x, bp.x), iy1 = fmaxf(bt.y, bp.y);
    float ix2 = fminf(bt.z, bp.z), iy2 = fminf(bt.w, bp.w);
    float inter = fmaxf(ix2 - ix1, 0.f) * fmaxf(iy2 - iy1, 0.f);
    float wt = bt.z - bt.x, ht = bt.w - bt.y;
    float wp = bp.z - bp.x, hp = bp.w - bp.y;
    float uni = wt * ht + wp * hp - inter + EPSF;
    float iou = inter / uni;
    float cw = fmaxf(bt.z, bp.z) - fminf(bt.x, bp.x);
    float ch = fmaxf(bt.w, bp.w) - fminf(bt.y, bp.y);
    float c2 = cw * cw + ch * ch + EPSF;
    float dx = bt.x + bt.z - bp.x - bp.z;
    float dy = bt.y + bt.w - bp.y - bp.w;
    float rho2 = (dx * dx + dy * dy) * 0.25f;
    float dat = atanf(wt / (ht + EPSF)) - atanf(wp / (hp + EPSF));
    float v = (4.0f / (float)(M_PI * M_PI)) * dat * dat;
    float alpha = v / (1.0f - iou + v + EPSF);
    return 1.0f - iou + rho2 / c2 + alpha * v;
}

// ---------------------------------------------------------------------------
// Fused pass: per-anchor assignment (threshold only) + losses + per-GT best.
// Stores exact {maxiou, tix} per anchor for the fixup pass.
// ---------------------------------------------------------------------------
__global__ void fused_kernel(const float* __restrict__ y_true,
                             const float4* __restrict__ bbox_true,
                             const float* __restrict__ conf_pred,
                             const float* __restrict__ logit_pred,
                             const float4* __restrict__ bbox_pred,
                             const float4* __restrict__ anchors,
                             int N, int P, int A, int C) {
    int n = blockIdx.y;
    int tid = threadIdx.x;
    int a = blockIdx.x * blockDim.x + tid;

    __shared__ float4 s_gt[MAXP];     // compacted valid GTs (ascending p)
    __shared__ float  s_area[MAXP];
    __shared__ short  s_orig[MAXP];
    __shared__ unsigned long long s_key[MAXP];
    __shared__ int    s_wcnt[4];
    __shared__ int    s_nv;

    {   // stable compaction (P <= 128)
        bool v = false; float4 g = {0,0,0,0};
        if (tid < P) {
            g = bbox_true[n * P + tid];
            v = (g.x > 0.f) || (g.y > 0.f) || (g.z > 0.f) || (g.w > 0.f);
            s_key[tid] = 0ull;
        }
        if (tid < 128) {
            unsigned m = __ballot_sync(0xffffffffu, v);
            int w = tid >> 5, lane = tid & 31;
            if (lane == 0) s_wcnt[w] = __popc(m);
            __syncthreads();
            if (tid == 0) s_nv = s_wcnt[0] + s_wcnt[1] + s_wcnt[2] + s_wcnt[3];
            int off = 0;
            for (int i = 0; i < w; i++) off += s_wcnt[i];
            if (v) {
                int pos = off + __popc(m & ((1u << lane) - 1u));
                s_gt[pos] = g;
                s_area[pos] = (g.z - g.x) * (g.w - g.y);
                s_orig[pos] = (short)tid;
            }
        } else {
            __syncthreads();
        }
        __syncthreads();
    }
    int nv = s_nv;

    float score = 0.f, cls = 0.f, bl = 0.f;
    int posc = 0;

    if (a < A) {
        float4 an = anchors[a];
        float areaa = (an.z - an.x) * (an.w - an.y);
        float bi = -1.0f, bd = 1.0f;   // best iou = bi/bd, first-index wins
        int tixc = 0;
        unsigned inv_a = ~(unsigned)a;
        #pragma unroll 2
        for (int i = 0; i < nv; i++) {
            float4 g = s_gt[i];
            float iw = fmaxf(fminf(an.z, g.z) - fmaxf(an.x, g.x), 0.f);
            float ih = fmaxf(fminf(an.w, g.w) - fmaxf(an.y, g.y), 0.f);
            float inter = iw * ih;
            float denom = areaa + s_area[i] - inter + EPSF;
            if (inter * bd > bi * denom) { bi = inter; bd = denom; tixc = i; }
            if (inter > 0.f) {
                float iou = inter / denom;
                unsigned long long key =
                    ((unsigned long long)__float_as_uint(iou) << 32) | inv_a;
                atomicMax(&s_key[i], key);
            }
        }
        float maxiou = (nv > 0) ? (bi / bd) : -1.0f;
        int tix = (nv > 0) ? (int)s_orig[tixc] : 0;

        float2 r; r.x = maxiou; r.y = __int_as_float(tix);
        g_amax[(size_t)n * A + a] = r;

        bool pos = (maxiou >= POS_THR);
        bool neg = (maxiou < NEG_THR);

        float pc = clipf(conf_pred[(size_t)n * A + a]);
        if (pos)      score = -__logf(pc);
        else if (neg) score = -__logf(1.0f - pc);

        if (pos) {
            posc = 1;
            const float4* qrow = reinterpret_cast<const float4*>(
                logit_pred + ((size_t)n * A + a) * C);
            const float4* trow = reinterpret_cast<const float4*>(
                y_true + ((size_t)n * P + tix) * C);
            for (int c4 = 0; c4 < C / 4; c4++) {
                float4 tv = trow[c4];
                float4 qv = qrow[c4];
                cls += focal_term(tv.x, qv.x) + focal_term(tv.y, qv.y)
                     + focal_term(tv.z, qv.z) + focal_term(tv.w, qv.w);
            }
            bl = ciou(s_gt[tixc], bbox_pred[(size_t)n * A + a]);
        }
    }

    // Block reduction -> per-(n,component) atomics
    unsigned mask = 0xffffffffu;
    #pragma unroll
    for (int off = 16; off > 0; off >>= 1) {
        score += __shfl_down_sync(mask, score, off);
        cls   += __shfl_down_sync(mask, cls, off);
        bl    += __shfl_down_sync(mask, bl, off);
        posc  += __shfl_down_sync(mask, posc, off);
    }
    __shared__ float rs0[8], rs1[8], rs2[8];
    __shared__ int   ri[8];
    int lane = tid & 31, warp = tid >> 5;
    if (lane == 0) { rs0[warp] = score; rs1[warp] = cls; rs2[warp] = bl; ri[warp] = posc; }
    __syncthreads();
    if (tid == 0) {
        float t0 = 0.f, t1 = 0.f, t2 = 0.f; int tc = 0;
        for (int w = 0; w < 8; w++) { t0 += rs0[w]; t1 += rs1[w]; t2 += rs2[w]; tc += ri[w]; }
        atomicAdd(&g_s.sumn[n * 3 + 0], (double)t0);
        atomicAdd(&g_s.sumn[n * 3 + 1], (double)t1);
        atomicAdd(&g_s.sumn[n * 3 + 2], (double)t2);
        if (tc) atomicAdd(&g_s.poscnt[n], tc);
    }
    // per-GT best anchor -> global
    if (tid < nv && s_key[tid] != 0ull)
        atomicMax(&g_s.gtkey[n * P + (int)s_orig[tid]], s_key[tid]);
}

// ---------------------------------------------------------------------------
// Fixup: apply low-quality overrides as deltas, fully parallel.
// Last block finalizes outputs.
// ---------------------------------------------------------------------------
__global__ void fixup_kernel(const float* __restrict__ y_true,
                             const float4* __restrict__ bbox_true,
                             const float* __restrict__ conf_pred,
                             const float* __restrict__ logit_pred,
                             const float4* __restrict__ bbox_pred,
                             float* __restrict__ out,
                             int N, int P, int A, int C) {
    int n = blockIdx.x;
    int tid = threadIdx.x;
    int lane = tid & 31, warp = tid >> 5;

    __shared__ float4 s_raw[MAXP];
    __shared__ int    s_ba[MAXP + 28]; // padded so scans can run past P safely
    __shared__ short  s_wp[MAXP];      // winner GT indices (compact, ascending)
    __shared__ int    s_wcnt[4];
    __shared__ int    s_nw;
    __shared__ bool   s_last;

    if (tid < MAXP + 28) s_ba[tid] = -1;
    __syncthreads();
    if (tid < P) {
        s_raw[tid] = bbox_true[n * P + tid];
        unsigned long long key = g_s.gtkey[n * P + tid];
        if (key != 0ull) s_ba[tid] = (int)(~(unsigned)key);
    }
    __syncthreads();

    // winner[p] = ba[p]>=0 and no later GT maps to the same anchor (last-wins);
    // independent O(P) scan per thread (pipelined LDS, no dependence chain)
    bool win = false;
    if (tid < P && s_ba[tid] >= 0) {
        int mya = s_ba[tid];
        bool dup = false;
        for (int q = tid + 1; q < P; q++) dup |= (s_ba[q] == mya);
        win = !dup;
    }
    // stable ballot compaction of winners
    if (tid < 128) {
        unsigned m = __ballot_sync(0xffffffffu, win);
        if (lane == 0) s_wcnt[warp] = __popc(m);
        __syncthreads();
        if (tid == 0) s_nw = s_wcnt[0] + s_wcnt[1] + s_wcnt[2] + s_wcnt[3];
        int off = 0;
        for (int i = 0; i < warp; i++) off += s_wcnt[i];
        if (win) s_wp[off + __popc(m & ((1u << lane) - 1u))] = (short)tid;
    }
    __syncthreads();
    int nw = s_nw;

    double d0 = 0.0, d1 = 0.0, d2 = 0.0;
    int dpc = 0;

    for (int wi = warp; wi < nw; wi += blockDim.x >> 5) {
        int p = s_wp[wi];          // new tix
        int a = s_ba[p];
        float2 am = g_amax[(size_t)n * A + a];  // exact values from fused pass
        float maxiou = am.x;
        int old_tix = __float_as_int(am.y);

        bool pos_t = (maxiou >= POS_THR);
        bool neg_t = (maxiou < NEG_THR);

        if (lane == 0 && !pos_t) {
            float pc = clipf(conf_pred[(size_t)n * A + a]);
            float ds = -__logf(pc);               // add pos score
            if (neg_t) ds -= -__logf(1.0f - pc);  // remove neg score
            d0 += (double)ds;
            dpc += 1;
        }
        if (!pos_t || old_tix != p) {
            const float* qrow = logit_pred + ((size_t)n * A + a) * C;
            const float* trow_new = y_true + ((size_t)n * P + p) * C;
            const float* trow_old = y_true + ((size_t)n * P + old_tix) * C;
            float dc = 0.f;
            for (int c = lane; c < C; c += 32) {
                float q = qrow[c];
                dc += focal_term(trow_new[c], q);
                if (pos_t) dc -= focal_term(trow_old[c], q);
            }
            #pragma unroll
            for (int off = 16; off > 0; off >>= 1)
                dc += __shfl_down_sync(0xffffffffu, dc, off);
            if (lane == 0) {
                d1 += (double)dc;
                float4 bp = bbox_pred[(size_t)n * A + a];
                float db = ciou(s_raw[p], bp);
                if (pos_t) db -= ciou(s_raw[old_tix], bp);
                d2 += (double)db;
            }
        }
    }
    if (lane == 0) {
        if (d0 != 0.0) atomicAdd(&g_s.sumn[n * 3 + 0], d0);
        if (d1 != 0.0) atomicAdd(&g_s.sumn[n * 3 + 1], d1);
        if (d2 != 0.0) atomicAdd(&g_s.sumn[n * 3 + 2], d2);
        if (dpc)       atomicAdd(&g_s.poscnt[n], dpc);
    }
    __syncthreads();
    if (tid == 0) {
        __threadfence();
        int d = atomicAdd(&g_s.done, 1);
        s_last = (d == N - 1);
    }
    __syncthreads();
    if (s_last && tid == 0) {
        __threadfence();
        double af = 0.0, t0 = 0.0, t1 = 0.0, t2 = 0.0;
        for (int nn = 0; nn < N; nn++) {
            int c = g_s.poscnt[nn];
            af += (double)(c > 1 ? c : 1);
            t0 += g_s.sumn[nn * 3 + 0];
            t1 += g_s.sumn[nn * 3 + 1];
            t2 += g_s.sumn[nn * 3 + 2];
        }
        double s[3] = {t0, t1, t2};
        #pragma unroll
        for (int i = 0; i < 3; i++) {
            float v = (float)(s[i] / af);
            if (isnan(v) || isinf(v)) v = 0.f;
            out[i] = v;
        }
    }
}

extern "C" void kernel_launch(void* const* d_in, const int* in_sizes, int n_in,
                              void* d_out, int out_size) {
    const float* y_true    = (const float*)d_in[0];
    const float* bbox_true = (const float*)d_in[1];
    const float* conf_pred = (const float*)d_in[2];
    const float* logit     = (const float*)d_in[3];
    const float* bbox_pred = (const float*)d_in[4];
    const float* anchors   = (const float*)d_in[5];

    int A = in_sizes[5] / 4;
    int N = in_sizes[2] / A;
    int C = in_sizes[3] / (N * A);
    int P = in_sizes[1] / (N * 4);

    void* scratch_addr = nullptr;
    cudaGetSymbolAddress(&scratch_addr, g_s);
    cudaMemsetAsync(scratch_addr, 0, sizeof(Scratch));

    int gx = (A + 255) / 256;
    fused_kernel<<<dim3(gx, N), 256>>>(
        y_true, (const float4*)bbox_true, conf_pred, logit,
        (const float4*)bbox_pred, (const float4*)anchors, N, P, A, C);
    fixup_kernel<<<N, 128>>>(
        y_true, (const float4*)bbox_true, conf_pred, logit,
        (const float4*)bbox_pred, (float*)d_out, N, P, A, C);
}

// round 7
// speedup vs baseline: 2.7313x; 1.0608x over previous
#include <cuda_runtime.h>
#include <math.h>

#define EPSF 1e-7f
#define POS_THR 0.5f
#define NEG_THR 0.4f
#define ALPHA_F 0.25f

#define MAXN 32
#define MAXP 100
#define MAXA 25600

// Contiguous scratch so one memset clears everything that must start at 0.
struct Scratch {
    unsigned long long gtkey[MAXN * MAXP]; // packed (iou_bits<<32)|~a per GT
    double             sumn[MAXN * 3];     // per-batch partial sums
    int                poscnt[MAXN];
    int                done_n[MAXN];       // per-image completed block counters
    int                done;               // completed fixup counter
};
__device__ Scratch g_s;
__device__ float2  g_amax[MAXN * MAXA];    // {maxiou, int_as_float(tix)} per anchor
                                           // (fully rewritten before any read)

__device__ __forceinline__ float clipf(float x) {
    return fminf(fmaxf(x, EPSF), 1.0f - EPSF);
}

__device__ __forceinline__ float focal_term(float t, float qraw) {
    float q  = clipf(qraw);
    float pt = t * q + (1.f - t) * (1.f - q);
    float at = t * ALPHA_F + (1.f - t) * (1.f - ALPHA_F);
    float om = 1.f - pt;
    return -at * om * om * __logf(pt);
}

__device__ __forceinline__ float ciou(float4 bt, float4 bp) {
    float ix1 = fmaxf(bt.x, bp.x), iy1 = fmaxf(bt.y, bp.y);
    float ix2 = fminf(bt.z, bp.z), iy2 = fminf(bt.w, bp.w);
    float inter = fmaxf(ix2 - ix1, 0.f) * fmaxf(iy2 - iy1, 0.f);
    float wt = bt.z - bt.x, ht = bt.w - bt.y;
    float wp = bp.z - bp.x, hp = bp.w - bp.y;
    float uni = wt * ht + wp * hp - inter + EPSF;
    float iou = inter / uni;
    float cw = fmaxf(bt.z, bp.z) - fminf(bt.x, bp.x);
    float ch = fmaxf(bt.w, bp.w) - fminf(bt.y, bp.y);
    float c2 = cw * cw + ch * ch + EPSF;
    float dx = bt.x + bt.z - bp.x - bp.z;
    float dy = bt.y + bt.w - bp.y - bp.w;
    float rho2 = (dx * dx + dy * dy) * 0.25f;
    float dat = atanf(wt / (ht + EPSF)) - atanf(wp / (hp + EPSF));
    float v = (4.0f / (float)(M_PI * M_PI)) * dat * dat;
    float alpha = v / (1.0f - iou + v + EPSF);
    return 1.0f - iou + rho2 / c2 + alpha * v;
}

// ---------------------------------------------------------------------------
// Single fused kernel: per-anchor assignment + losses + per-GT best anchor;
// last block per image applies low-quality-override deltas; last fixup block
// finalizes the three outputs.
// ---------------------------------------------------------------------------
__global__ void __launch_bounds__(256, 6)
fused_kernel(const float* __restrict__ y_true,
             const float4* __restrict__ bbox_true,
             const float* __restrict__ conf_pred,
             const float* __restrict__ logit_pred,
             const float4* __restrict__ bbox_pred,
             const float4* __restrict__ anchors,
             float* __restrict__ out,
             int N, int P, int A, int C) {
    int n = blockIdx.y;
    int tid = threadIdx.x;
    int a = blockIdx.x * blockDim.x + tid;
    int lane = tid & 31, warp = tid >> 5;

    __shared__ float4 s_gt[MAXP];     // compacted valid GTs (ascending p)
    __shared__ float  s_area[MAXP];
    __shared__ short  s_orig[MAXP];
    __shared__ float4 s_rawgt[MAXP];  // raw GT boxes (original indexing)
    __shared__ unsigned long long s_key[MAXP];
    __shared__ int    s_wcnt[4];
    __shared__ int    s_nv;

    {   // stable compaction (P <= 128)
        bool v = false; float4 g = {0,0,0,0};
        if (tid < P) {
            g = bbox_true[n * P + tid];
            s_rawgt[tid] = g;
            v = (g.x > 0.f) || (g.y > 0.f) || (g.z > 0.f) || (g.w > 0.f);
            s_key[tid] = 0ull;
        }
        if (tid < 128) {
            unsigned m = __ballot_sync(0xffffffffu, v);
            if (lane == 0) s_wcnt[warp] = __popc(m);
            __syncthreads();
            if (tid == 0) s_nv = s_wcnt[0] + s_wcnt[1] + s_wcnt[2] + s_wcnt[3];
            int off = 0;
            for (int i = 0; i < warp; i++) off += s_wcnt[i];
            if (v) {
                int pos = off + __popc(m & ((1u << lane) - 1u));
                s_gt[pos] = g;
                s_area[pos] = (g.z - g.x) * (g.w - g.y);
                s_orig[pos] = (short)tid;
            }
        } else {
            __syncthreads();
        }
        __syncthreads();
    }
    int nv = s_nv;

    float score = 0.f, cls = 0.f, bl = 0.f;
    int posc = 0;

    if (a < A) {
        float4 an = anchors[a];
        float areaa = (an.z - an.x) * (an.w - an.y);
        float bi = -1.0f, bd = 1.0f;   // best iou = bi/bd, first-index wins
        int tixc = 0;
        unsigned inv_a = ~(unsigned)a;
        #pragma unroll 4
        for (int i = 0; i < nv; i++) {
            float4 g = s_gt[i];
            float iw = fmaxf(fminf(an.z, g.z) - fmaxf(an.x, g.x), 0.f);
            float ih = fmaxf(fminf(an.w, g.w) - fmaxf(an.y, g.y), 0.f);
            float inter = iw * ih;
            float denom = areaa + s_area[i] - inter + EPSF;
            if (inter * bd > bi * denom) { bi = inter; bd = denom; tixc = i; }
            if (inter > 0.f) {
                float iou = inter / denom;
                unsigned long long key =
                    ((unsigned long long)__float_as_uint(iou) << 32) | inv_a;
                atomicMax(&s_key[i], key);
            }
        }
        float maxiou = (nv > 0) ? (bi / bd) : -1.0f;
        int tix = (nv > 0) ? (int)s_orig[tixc] : 0;

        float2 r; r.x = maxiou; r.y = __int_as_float(tix);
        g_amax[(size_t)n * A + a] = r;

        bool pos = (maxiou >= POS_THR);
        bool neg = (maxiou < NEG_THR);

        float pc = clipf(conf_pred[(size_t)n * A + a]);
        if (pos)      score = -__logf(pc);
        else if (neg) score = -__logf(1.0f - pc);

        if (pos) {
            posc = 1;
            const float4* qrow = reinterpret_cast<const float4*>(
                logit_pred + ((size_t)n * A + a) * C);
            const float4* trow = reinterpret_cast<const float4*>(
                y_true + ((size_t)n * P + tix) * C);
            for (int c4 = 0; c4 < C / 4; c4++) {
                float4 tv = trow[c4];
                float4 qv = qrow[c4];
                cls += focal_term(tv.x, qv.x) + focal_term(tv.y, qv.y)
                     + focal_term(tv.z, qv.z) + focal_term(tv.w, qv.w);
            }
            bl = ciou(s_gt[tixc], bbox_pred[(size_t)n * A + a]);
        }
    }
    __syncthreads();
    // per-GT best anchor -> global (before the reduction to overlap latency)
    if (tid < nv && s_key[tid] != 0ull)
        atomicMax(&g_s.gtkey[n * P + (int)s_orig[tid]], s_key[tid]);

    // Block reduction -> per-(n,component) atomics
    unsigned mask = 0xffffffffu;
    #pragma unroll
    for (int off = 16; off > 0; off >>= 1) {
        score += __shfl_down_sync(mask, score, off);
        cls   += __shfl_down_sync(mask, cls, off);
        bl    += __shfl_down_sync(mask, bl, off);
        posc  += __shfl_down_sync(mask, posc, off);
    }
    __shared__ float rs0[8], rs1[8], rs2[8];
    __shared__ int   ri[8];
    if (lane == 0) { rs0[warp] = score; rs1[warp] = cls; rs2[warp] = bl; ri[warp] = posc; }
    __syncthreads();
    if (tid == 0) {
        float t0 = 0.f, t1 = 0.f, t2 = 0.f; int tc = 0;
        for (int w = 0; w < 8; w++) { t0 += rs0[w]; t1 += rs1[w]; t2 += rs2[w]; tc += ri[w]; }
        atomicAdd(&g_s.sumn[n * 3 + 0], (double)t0);
        atomicAdd(&g_s.sumn[n * 3 + 1], (double)t1);
        atomicAdd(&g_s.sumn[n * 3 + 2], (double)t2);
        if (tc) atomicAdd(&g_s.poscnt[n], tc);
    }

    // ------------- per-image completion gate -------------
    __threadfence();
    __shared__ bool s_lastn;
    if (tid == 0) {
        int d = atomicAdd(&g_s.done_n[n], 1);
        s_lastn = (d == (int)gridDim.x - 1);
    }
    __syncthreads();
    if (!s_lastn) return;
    __threadfence();   // acquire: all blocks of image n have published gtkey/sums

    // ------------- FIXUP for image n (this block only) -------------
    __shared__ int    s_ba[MAXP + 28];
    __shared__ short  s_wp[MAXP];
    __shared__ int    s_nw;
    __shared__ bool   s_last;

    if (tid < MAXP + 28) s_ba[tid] = -1;
    __syncthreads();
    if (tid < P) {
        unsigned long long key = g_s.gtkey[n * P + tid];
        if (key != 0ull) s_ba[tid] = (int)(~(unsigned)key);
    }
    __syncthreads();

    // winner = lowq GT with no later GT mapping to same anchor (last-wins)
    bool win = false;
    if (tid < P && s_ba[tid] >= 0) {
        int mya = s_ba[tid];
        bool dup = false;
        for (int q = tid + 1; q < P; q++) dup |= (s_ba[q] == mya);
        win = !dup;
    }
    if (tid < 128) {
        unsigned m = __ballot_sync(0xffffffffu, win);
        if (lane == 0) s_wcnt[warp] = __popc(m);
        __syncthreads();
        if (tid == 0) s_nw = s_wcnt[0] + s_wcnt[1] + s_wcnt[2] + s_wcnt[3];
        int off = 0;
        for (int i = 0; i < warp; i++) off += s_wcnt[i];
        if (win) s_wp[off + __popc(m & ((1u << lane) - 1u))] = (short)tid;
    } else {
        __syncthreads();
    }
    __syncthreads();
    int nw = s_nw;

    double d0 = 0.0, d1 = 0.0, d2 = 0.0;
    int dpc = 0;

    for (int wi = warp; wi < nw; wi += (int)blockDim.x >> 5) {
        int p = s_wp[wi];          // new tix
        int ba = s_ba[p];
        float2 am = g_amax[(size_t)n * A + ba];  // exact fused-pass values
        float maxiou = am.x;
        int old_tix = __float_as_int(am.y);

        bool pos_t = (maxiou >= POS_THR);
        bool neg_t = (maxiou < NEG_THR);

        if (lane == 0 && !pos_t) {
            float pc = clipf(conf_pred[(size_t)n * A + ba]);
            float ds = -__logf(pc);               // add pos score
            if (neg_t) ds -= -__logf(1.0f - pc);  // remove neg score
            d0 += (double)ds;
            dpc += 1;
        }
        if (!pos_t || old_tix != p) {
            const float* qrow = logit_pred + ((size_t)n * A + ba) * C;
            const float* trow_new = y_true + ((size_t)n * P + p) * C;
            const float* trow_old = y_true + ((size_t)n * P + old_tix) * C;
            float dc = 0.f;
            for (int c = lane; c < C; c += 32) {
                float q = qrow[c];
                dc += focal_term(trow_new[c], q);
                if (pos_t) dc -= focal_term(trow_old[c], q);
            }
            #pragma unroll
            for (int off = 16; off > 0; off >>= 1)
                dc += __shfl_down_sync(0xffffffffu, dc, off);
            if (lane == 0) {
                d1 += (double)dc;
                float4 bp = bbox_pred[(size_t)n * A + ba];
                float db = ciou(s_rawgt[p], bp);
                if (pos_t) db -= ciou(s_rawgt[old_tix], bp);
                d2 += (double)db;
            }
        }
    }
    if (lane == 0) {
        if (d0 != 0.0) atomicAdd(&g_s.sumn[n * 3 + 0], d0);
        if (d1 != 0.0) atomicAdd(&g_s.sumn[n * 3 + 1], d1);
        if (d2 != 0.0) atomicAdd(&g_s.sumn[n * 3 + 2], d2);
        if (dpc)       atomicAdd(&g_s.poscnt[n], dpc);
    }
    __syncthreads();
    __threadfence();
    if (tid == 0) {
        int d = atomicAdd(&g_s.done, 1);
        s_last = (d == N - 1);
    }
    __syncthreads();
    if (s_last && tid == 0) {
        __threadfence();
        double af = 0.0, t0 = 0.0, t1 = 0.0, t2 = 0.0;
        for (int nn = 0; nn < N; nn++) {
            int c = g_s.poscnt[nn];
            af += (double)(c > 1 ? c : 1);
            t0 += g_s.sumn[nn * 3 + 0];
            t1 += g_s.sumn[nn * 3 + 1];
            t2 += g_s.sumn[nn * 3 + 2];
        }
        double s[3] = {t0, t1, t2};
        #pragma unroll
        for (int i = 0; i < 3; i++) {
            float v = (float)(s[i] / af);
            if (isnan(v) || isinf(v)) v = 0.f;
            out[i] = v;
        }
    }
}

extern "C" void kernel_launch(void* const* d_in, const int* in_sizes, int n_in,
                              void* d_out, int out_size) {
    const float* y_true    = (const float*)d_in[0];
    const float* bbox_true = (const float*)d_in[1];
    const float* conf_pred = (const float*)d_in[2];
    const float* logit     = (const float*)d_in[3];
    const float* bbox_pred = (const float*)d_in[4];
    const float* anchors   = (const float*)d_in[5];

    int A = in_sizes[5] / 4;
    int N = in_sizes[2] / A;
    int C = in_sizes[3] / (N * A);
    int P = in_sizes[1] / (N * 4);

    void* scratch_addr = nullptr;
    cudaGetSymbolAddress(&scratch_addr, g_s);
    cudaMemsetAsync(scratch_addr, 0, sizeof(Scratch));

    int gx = (A + 255) / 256;
    fused_kernel<<<dim3(gx, N), 256>>>(
        y_true, (const float4*)bbox_true, conf_pred, logit,
        (const float4*)bbox_pred, (const float4*)anchors,
        (float*)d_out, N, P, A, C);
}

// round 8
// speedup vs baseline: 2.9840x; 1.0925x over previous
#include <cuda_runtime.h>
#include <math.h>

#define EPSF 1e-7f
#define POS_THR 0.5f
#define NEG_THR 0.4f
#define ALPHA_F 0.25f

#define MAXN 32
#define MAXP 100
#define MAXA 25600

// Contiguous scratch so one memset clears everything that must start at 0.
struct Scratch {
    unsigned long long gtkey[MAXN * MAXP]; // packed (iou_bits<<32)|~a per GT
    double             sumn[MAXN * 3];     // per-batch partial sums
    int                poscnt[MAXN];
    int                done_n[MAXN];       // per-image completed block counters
    int                done;               // completed fixup counter
};
__device__ Scratch g_s;
__device__ float2  g_amax[MAXN * MAXA];    // {maxiou, int_as_float(tix)} per anchor

__device__ __forceinline__ float clipf(float x) {
    return fminf(fmaxf(x, EPSF), 1.0f - EPSF);
}

__device__ __forceinline__ float focal_term(float t, float qraw) {
    float q  = clipf(qraw);
    float pt = t * q + (1.f - t) * (1.f - q);
    float at = t * ALPHA_F + (1.f - t) * (1.f - ALPHA_F);
    float om = 1.f - pt;
    return -at * om * om * __logf(pt);
}

__device__ __forceinline__ float ciou(float4 bt, float4 bp) {
    float ix1 = fmaxf(bt.x, bp.x), iy1 = fmaxf(bt.y, bp.y);
    float ix2 = fminf(bt.z, bp.z), iy2 = fminf(bt.w, bp.w);
    float inter = fmaxf(ix2 - ix1, 0.f) * fmaxf(iy2 - iy1, 0.f);
    float wt = bt.z - bt.x, ht = bt.w - bt.y;
    float wp = bp.z - bp.x, hp = bp.w - bp.y;
    float uni = wt * ht + wp * hp - inter + EPSF;
    float iou = inter / uni;
    float cw = fmaxf(bt.z, bp.z) - fminf(bt.x, bp.x);
    float ch = fmaxf(bt.w, bp.w) - fminf(bt.y, bp.y);
    float c2 = cw * cw + ch * ch + EPSF;
    float dx = bt.x + bt.z - bp.x - bp.z;
    float dy = bt.y + bt.w - bp.y - bp.w;
    float rho2 = (dx * dx + dy * dy) * 0.25f;
    float dat = atanf(wt / (ht + EPSF)) - atanf(wp / (hp + EPSF));
    float v = (4.0f / (float)(M_PI * M_PI)) * dat * dat;
    float alpha = v / (1.0f - iou + v + EPSF);
    return 1.0f - iou + rho2 / c2 + alpha * v;
}

// ---------------------------------------------------------------------------
// Single fused kernel with per-block GT culling against the block's anchor
// union bbox. Skipped GTs have iou == 0 for every anchor in the block, which
// cannot change any loss (pos needs iou >= 0.5; gt-best atomics need inter>0;
// argmax ties at 0 only affect tix, which is consumed only when pos).
// ---------------------------------------------------------------------------
__global__ void __launch_bounds__(256, 6)
fused_kernel(const float* __restrict__ y_true,
             const float4* __restrict__ bbox_true,
             const float* __restrict__ conf_pred,
             const float* __restrict__ logit_pred,
             const float4* __restrict__ bbox_pred,
             const float4* __restrict__ anchors,
             float* __restrict__ out,
             int N, int P, int A, int C) {
    int n = blockIdx.y;
    int tid = threadIdx.x;
    int a = blockIdx.x * blockDim.x + tid;
    int lane = tid & 31, warp = tid >> 5;

    __shared__ float4 s_gt[MAXP];     // compacted valid GTs (ascending p)
    __shared__ short  s_orig[MAXP];
    __shared__ float4 s_rawgt[MAXP];  // raw GT boxes (original indexing)
    __shared__ unsigned long long s_key[MAXP];
    __shared__ float4 s_fgt[MAXP];    // block-filtered GTs
    __shared__ float  s_farea[MAXP];
    __shared__ short  s_fci[MAXP];    // filtered -> compact index
    __shared__ int    s_wcnt[4];
    __shared__ int    s_nv, s_fnv;
    __shared__ float  s_ubb[4];       // block anchor union bbox

    // Load anchor (or empty box for tail threads)
    float4 an;
    if (a < A) an = anchors[a];
    else { an.x = 1e30f; an.y = 1e30f; an.z = -1e30f; an.w = -1e30f; }

    // Block union bbox of anchors: warp shuffle reduce, then cross-warp
    {
        float x1 = an.x, y1 = an.y, x2 = an.z, y2 = an.w;
        #pragma unroll
        for (int off = 16; off > 0; off >>= 1) {
            x1 = fminf(x1, __shfl_xor_sync(0xffffffffu, x1, off));
            y1 = fminf(y1, __shfl_xor_sync(0xffffffffu, y1, off));
            x2 = fmaxf(x2, __shfl_xor_sync(0xffffffffu, x2, off));
            y2 = fmaxf(y2, __shfl_xor_sync(0xffffffffu, y2, off));
        }
        __shared__ float swx1[8], swy1[8], swx2[8], swy2[8];
        if (lane == 0) { swx1[warp] = x1; swy1[warp] = y1; swx2[warp] = x2; swy2[warp] = y2; }
        __syncthreads();
        if (tid == 0) {
            float a1 = swx1[0], b1 = swy1[0], a2 = swx2[0], b2 = swy2[0];
            for (int w = 1; w < 8; w++) {
                a1 = fminf(a1, swx1[w]); b1 = fminf(b1, swy1[w]);
                a2 = fmaxf(a2, swx2[w]); b2 = fmaxf(b2, swy2[w]);
            }
            s_ubb[0] = a1; s_ubb[1] = b1; s_ubb[2] = a2; s_ubb[3] = b2;
        }
    }

    {   // stable compaction of valid GTs (P <= 128)
        bool v = false; float4 g = {0,0,0,0};
        if (tid < P) {
            g = bbox_true[n * P + tid];
            s_rawgt[tid] = g;
            v = (g.x > 0.f) || (g.y > 0.f) || (g.z > 0.f) || (g.w > 0.f);
            s_key[tid] = 0ull;
        }
        if (tid < 128) {
            unsigned m = __ballot_sync(0xffffffffu, v);
            if (lane == 0) s_wcnt[warp] = __popc(m);
            __syncthreads();
            if (tid == 0) s_nv = s_wcnt[0] + s_wcnt[1] + s_wcnt[2] + s_wcnt[3];
            int off = 0;
            for (int i = 0; i < warp; i++) off += s_wcnt[i];
            if (v) {
                int pos = off + __popc(m & ((1u << lane) - 1u));
                s_gt[pos] = g;
                s_orig[pos] = (short)tid;
            }
        } else {
            __syncthreads();
        }
        __syncthreads();
    }
    int nv = s_nv;

    {   // filter compacted GTs against the block union bbox
        bool keep = false; float4 g = {0,0,0,0};
        if (tid < nv) {
            g = s_gt[tid];
            keep = (g.x < s_ubb[2]) && (g.z > s_ubb[0]) &&
                   (g.y < s_ubb[3]) && (g.w > s_ubb[1]);
        }
        if (tid < 128) {
            unsigned m = __ballot_sync(0xffffffffu, keep);
            if (lane == 0) s_wcnt[warp] = __popc(m);
            __syncthreads();
            if (tid == 0) s_fnv = s_wcnt[0] + s_wcnt[1] + s_wcnt[2] + s_wcnt[3];
            int off = 0;
            for (int i = 0; i < warp; i++) off += s_wcnt[i];
            if (keep) {
                int pos = off + __popc(m & ((1u << lane) - 1u));
                s_fgt[pos] = g;
                s_farea[pos] = (g.z - g.x) * (g.w - g.y);
                s_fci[pos] = (short)tid;
            }
        } else {
            __syncthreads();
        }
        __syncthreads();
    }
    int fnv = s_fnv;

    float score = 0.f, cls = 0.f, bl = 0.f;
    int posc = 0;

    if (a < A) {
        float areaa = (an.z - an.x) * (an.w - an.y);
        float bi = -1.0f, bd = 1.0f;   // best iou = bi/bd, first-index wins
        int tixc = 0;
        unsigned inv_a = ~(unsigned)a;
        #pragma unroll 4
        for (int i = 0; i < fnv; i++) {
            float4 g = s_fgt[i];
            float iw = fmaxf(fminf(an.z, g.z) - fmaxf(an.x, g.x), 0.f);
            float ih = fmaxf(fminf(an.w, g.w) - fmaxf(an.y, g.y), 0.f);
            float inter = iw * ih;
            float denom = areaa + s_farea[i] - inter + EPSF;
            if (inter * bd > bi * denom) { bi = inter; bd = denom; tixc = i; }
            if (inter > 0.f) {
                float iou = inter / denom;
                unsigned long long key =
                    ((unsigned long long)__float_as_uint(iou) << 32) | inv_a;
                atomicMax(&s_key[(int)s_fci[i]], key);
            }
        }
        float maxiou; int tix;
        if (fnv > 0)      { maxiou = bi / bd; tix = (int)s_orig[(int)s_fci[tixc]]; }
        else if (nv > 0)  { maxiou = 0.0f;    tix = (int)s_orig[0]; }
        else              { maxiou = -1.0f;   tix = 0; }

        float2 r; r.x = maxiou; r.y = __int_as_float(tix);
        g_amax[(size_t)n * A + a] = r;

        bool pos = (maxiou >= POS_THR);
        bool neg = (maxiou < NEG_THR);

        float pc = clipf(conf_pred[(size_t)n * A + a]);
        if (pos)      score = -__logf(pc);
        else if (neg) score = -__logf(1.0f - pc);

        if (pos) {
            posc = 1;
            const float4* qrow = reinterpret_cast<const float4*>(
                logit_pred + ((size_t)n * A + a) * C);
            const float4* trow = reinterpret_cast<const float4*>(
                y_true + ((size_t)n * P + tix) * C);
            for (int c4 = 0; c4 < C / 4; c4++) {
                float4 tv = trow[c4];
                float4 qv = qrow[c4];
                cls += focal_term(tv.x, qv.x) + focal_term(tv.y, qv.y)
                     + focal_term(tv.z, qv.z) + focal_term(tv.w, qv.w);
            }
            bl = ciou(s_fgt[tixc], bbox_pred[(size_t)n * A + a]);
        }
    }
    __syncthreads();
    // per-GT best anchor -> global
    if (tid < nv && s_key[tid] != 0ull)
        atomicMax(&g_s.gtkey[n * P + (int)s_orig[tid]], s_key[tid]);

    // Block reduction -> per-(n,component) atomics
    unsigned mask = 0xffffffffu;
    #pragma unroll
    for (int off = 16; off > 0; off >>= 1) {
        score += __shfl_down_sync(mask, score, off);
        cls   += __shfl_down_sync(mask, cls, off);
        bl    += __shfl_down_sync(mask, bl, off);
        posc  += __shfl_down_sync(mask, posc, off);
    }
    __shared__ float rs0[8], rs1[8], rs2[8];
    __shared__ int   ri[8];
    if (lane == 0) { rs0[warp] = score; rs1[warp] = cls; rs2[warp] = bl; ri[warp] = posc; }
    __syncthreads();
    if (tid == 0) {
        float t0 = 0.f, t1 = 0.f, t2 = 0.f; int tc = 0;
        for (int w = 0; w < 8; w++) { t0 += rs0[w]; t1 += rs1[w]; t2 += rs2[w]; tc += ri[w]; }
        atomicAdd(&g_s.sumn[n * 3 + 0], (double)t0);
        atomicAdd(&g_s.sumn[n * 3 + 1], (double)t1);
        atomicAdd(&g_s.sumn[n * 3 + 2], (double)t2);
        if (tc) atomicAdd(&g_s.poscnt[n], tc);
    }

    // ------------- per-image completion gate -------------
    __threadfence();
    __shared__ bool s_lastn;
    if (tid == 0) {
        int d = atomicAdd(&g_s.done_n[n], 1);
        s_lastn = (d == (int)gridDim.x - 1);
    }
    __syncthreads();
    if (!s_lastn) return;
    __threadfence();   // all blocks of image n have published gtkey/sums

    // ------------- FIXUP for image n (this block only) -------------
    __shared__ int    s_ba[MAXP + 28];
    __shared__ short  s_wp[MAXP];
    __shared__ int    s_nw;
    __shared__ bool   s_last;

    if (tid < MAXP + 28) s_ba[tid] = -1;
    __syncthreads();
    if (tid < P) {
        unsigned long long key = g_s.gtkey[n * P + tid];
        if (key != 0ull) s_ba[tid] = (int)(~(unsigned)key);
    }
    __syncthreads();

    bool win = false;
    if (tid < P && s_ba[tid] >= 0) {
        int mya = s_ba[tid];
        bool dup = false;
        for (int q = tid + 1; q < P; q++) dup |= (s_ba[q] == mya);
        win = !dup;
    }
    if (tid < 128) {
        unsigned m = __ballot_sync(0xffffffffu, win);
        if (lane == 0) s_wcnt[warp] = __popc(m);
        __syncthreads();
        if (tid == 0) s_nw = s_wcnt[0] + s_wcnt[1] + s_wcnt[2] + s_wcnt[3];
        int off = 0;
        for (int i = 0; i < warp; i++) off += s_wcnt[i];
        if (win) s_wp[off + __popc(m & ((1u << lane) - 1u))] = (short)tid;
    } else {
        __syncthreads();
    }
    __syncthreads();
    int nw = s_nw;

    double d0 = 0.0, d1 = 0.0, d2 = 0.0;
    int dpc = 0;

    for (int wi = warp; wi < nw; wi += (int)blockDim.x >> 5) {
        int p = s_wp[wi];          // new tix
        int ba = s_ba[p];
        float2 am = g_amax[(size_t)n * A + ba];
        float maxiou = am.x;
        int old_tix = __float_as_int(am.y);

        bool pos_t = (maxiou >= POS_THR);
        bool neg_t = (maxiou < NEG_THR);

        if (lane == 0 && !pos_t) {
            float pc = clipf(conf_pred[(size_t)n * A + ba]);
            float ds = -__logf(pc);
            if (neg_t) ds -= -__logf(1.0f - pc);
            d0 += (double)ds;
            dpc += 1;
        }
        if (!pos_t || old_tix != p) {
            const float* qrow = logit_pred + ((size_t)n * A + ba) * C;
            const float* trow_new = y_true + ((size_t)n * P + p) * C;
            const float* trow_old = y_true + ((size_t)n * P + old_tix) * C;
            float dc = 0.f;
            for (int c = lane; c < C; c += 32) {
                float q = qrow[c];
                dc += focal_term(trow_new[c], q);
                if (pos_t) dc -= focal_term(trow_old[c], q);
            }
            #pragma unroll
            for (int off = 16; off > 0; off >>= 1)
                dc += __shfl_down_sync(0xffffffffu, dc, off);
            if (lane == 0) {
                d1 += (double)dc;
                float4 bp = bbox_pred[(size_t)n * A + ba];
                float db = ciou(s_rawgt[p], bp);
                if (pos_t) db -= ciou(s_rawgt[old_tix], bp);
                d2 += (double)db;
            }
        }
    }
    if (lane == 0) {
        if (d0 != 0.0) atomicAdd(&g_s.sumn[n * 3 + 0], d0);
        if (d1 != 0.0) atomicAdd(&g_s.sumn[n * 3 + 1], d1);
        if (d2 != 0.0) atomicAdd(&g_s.sumn[n * 3 + 2], d2);
        if (dpc)       atomicAdd(&g_s.poscnt[n], dpc);
    }
    __syncthreads();
    __threadfence();
    if (tid == 0) {
        int d = atomicAdd(&g_s.done, 1);
        s_last = (d == N - 1);
    }
    __syncthreads();
    if (s_last && tid == 0) {
        __threadfence();
        double af = 0.0, t0 = 0.0, t1 = 0.0, t2 = 0.0;
        for (int nn = 0; nn < N; nn++) {
            int c = g_s.poscnt[nn];
            af += (double)(c > 1 ? c : 1);
            t0 += g_s.sumn[nn * 3 + 0];
            t1 += g_s.sumn[nn * 3 + 1];
            t2 += g_s.sumn[nn * 3 + 2];
        }
        double s[3] = {t0, t1, t2};
        #pragma unroll
        for (int i = 0; i < 3; i++) {
            float v = (float)(s[i] / af);
            if (isnan(v) || isinf(v)) v = 0.f;
            out[i] = v;
        }
    }
}

extern "C" void kernel_launch(void* const* d_in, const int* in_sizes, int n_in,
                              void* d_out, int out_size) {
    const float* y_true    = (const float*)d_in[0];
    const float* bbox_true = (const float*)d_in[1];
    const float* conf_pred = (const float*)d_in[2];
    const float* logit     = (const float*)d_in[3];
    const float* bbox_pred = (const float*)d_in[4];
    const float* anchors   = (const float*)d_in[5];

    int A = in_sizes[5] / 4;
    int N = in_sizes[2] / A;
    int C = in_sizes[3] / (N * A);
    int P = in_sizes[1] / (N * 4);

    void* scratch_addr = nullptr;
    cudaGetSymbolAddress(&scratch_addr, g_s);
    cudaMemsetAsync(scratch_addr, 0, sizeof(Scratch));

    int gx = (A + 255) / 256;
    fused_kernel<<<dim3(gx, N), 256>>>(
        y_true, (const float4*)bbox_true, conf_pred, logit,
        (const float4*)bbox_pred, (const float4*)anchors,
        (float*)d_out, N, P, A, C);
}